// round 1
// baseline (speedup 1.0000x reference)
#include <cuda_runtime.h>
#include <math.h>

// NeuralODE: z0 = enc(y0); 100 Tsit5 steps of MLP(64->32->32->64, tanh) field;
// ys = dec(zs). Outputs: [ys (B,T,64) | zs (B,T,64)] in d_out.
//
// Layout: 1 warp owns NB=4 batch elements, state = 2 floats/lane.
// Weights transposed in SMEM (conflict-free per-lane loads); stage vectors
// exchanged via per-warp SMEM buffer read back as float4 broadcasts.

namespace {

constexpr int kB = 4096;
constexpr int kT = 101;
constexpr int kH = 64;
constexpr int NSTEPS = kT - 1;

constexpr int NB = 4;       // batch elements per warp
constexpr int WARPS = 4;    // warps per block
constexpr int THREADS = WARPS * 32;
constexpr int ELEMS_PER_BLOCK = WARPS * NB;   // 16
constexpr int GRID = kB / ELEMS_PER_BLOCK;    // 256

// Tsit5 tableau
__device__ __constant__ float cA21 = 0.161f;
__device__ __constant__ float cA31 = -0.008480655492356989f;
__device__ __constant__ float cA32 = 0.335480655492357f;
__device__ __constant__ float cA41 = 2.8971530571054935f;
__device__ __constant__ float cA42 = -6.359448489975075f;
__device__ __constant__ float cA43 = 4.3622954328695815f;
__device__ __constant__ float cA51 = 5.325864828439257f;
__device__ __constant__ float cA52 = -11.748883564062828f;
__device__ __constant__ float cA53 = 7.4955393428898365f;
__device__ __constant__ float cA54 = -0.09249506636175525f;
__device__ __constant__ float cA61 = 5.86145544294642f;
__device__ __constant__ float cA62 = -12.92096931784711f;
__device__ __constant__ float cA63 = 8.159367898576159f;
__device__ __constant__ float cA64 = -0.071584973281401f;
__device__ __constant__ float cA65 = -0.028269050394068383f;
__device__ __constant__ float cB1 = 0.09646076681806523f;
__device__ __constant__ float cB2 = 0.01f;
__device__ __constant__ float cB3 = 0.4798896504144996f;
__device__ __constant__ float cB4 = 1.379008574103742f;
__device__ __constant__ float cB5 = -3.290069515436081f;
__device__ __constant__ float cB6 = 2.324710524099774f;

__device__ __forceinline__ float tanh_f(float x) {
    // tanh(x) = sign(x) * (1 - e) / (1 + e), e = exp(-2|x|). ~1e-6 rel err.
    float ax = fabsf(x);
    float e = __expf(-2.0f * ax);
    float t = __fdividef(1.0f - e, 1.0f + e);
    return copysignf(t, x);
}

// 64->32 tanh, 32->32 tanh, 32->64 MLP. Input vector (64 per element) must
// already be in su (NB rows of 64 floats). Overwrites su rows with hidden
// activations. Outputs per lane: olo[e] = out[lane], ohi[e] = out[lane+32].
__device__ __forceinline__ void mlp_eval(
    const float* __restrict__ sW1T, const float* __restrict__ sW2T,
    const float* __restrict__ sW3T,
    float b1r, float b2r, float b3lo, float b3hi,
    float* su, int lane, float* olo, float* ohi)
{
    // ---- layer 1: h1[j] = tanh(b1[j] + sum_{k<64} u[k] * W1[j,k]) ----
    float a[NB];
#pragma unroll
    for (int e = 0; e < NB; e++) a[e] = b1r;
#pragma unroll
    for (int kc = 0; kc < 16; kc++) {
        float4 v[NB];
#pragma unroll
        for (int e = 0; e < NB; e++)
            v[e] = reinterpret_cast<const float4*>(su)[e * 16 + kc];
        float w0 = sW1T[(4 * kc + 0) * 32 + lane];
        float w1 = sW1T[(4 * kc + 1) * 32 + lane];
        float w2 = sW1T[(4 * kc + 2) * 32 + lane];
        float w3 = sW1T[(4 * kc + 3) * 32 + lane];
#pragma unroll
        for (int e = 0; e < NB; e++) {
            a[e] = fmaf(v[e].x, w0, a[e]);
            a[e] = fmaf(v[e].y, w1, a[e]);
            a[e] = fmaf(v[e].z, w2, a[e]);
            a[e] = fmaf(v[e].w, w3, a[e]);
        }
    }
#pragma unroll
    for (int e = 0; e < NB; e++) a[e] = tanh_f(a[e]);
    __syncwarp();
#pragma unroll
    for (int e = 0; e < NB; e++) su[e * 64 + lane] = a[e];
    __syncwarp();

    // ---- layer 2: h2[j] = tanh(b2[j] + sum_{k<32} h1[k] * W2[j,k]) ----
    float a2[NB];
#pragma unroll
    for (int e = 0; e < NB; e++) a2[e] = b2r;
#pragma unroll
    for (int kc = 0; kc < 8; kc++) {
        float4 v[NB];
#pragma unroll
        for (int e = 0; e < NB; e++)
            v[e] = reinterpret_cast<const float4*>(su)[e * 16 + kc];
        float w0 = sW2T[(4 * kc + 0) * 32 + lane];
        float w1 = sW2T[(4 * kc + 1) * 32 + lane];
        float w2 = sW2T[(4 * kc + 2) * 32 + lane];
        float w3 = sW2T[(4 * kc + 3) * 32 + lane];
#pragma unroll
        for (int e = 0; e < NB; e++) {
            a2[e] = fmaf(v[e].x, w0, a2[e]);
            a2[e] = fmaf(v[e].y, w1, a2[e]);
            a2[e] = fmaf(v[e].z, w2, a2[e]);
            a2[e] = fmaf(v[e].w, w3, a2[e]);
        }
    }
#pragma unroll
    for (int e = 0; e < NB; e++) a2[e] = tanh_f(a2[e]);
    __syncwarp();
#pragma unroll
    for (int e = 0; e < NB; e++) su[e * 64 + lane] = a2[e];
    __syncwarp();

    // ---- layer 3: o[i] = b3[i] + sum_{k<32} h2[k] * W3[i,k], i < 64 ----
    float c0[NB], c1[NB];
#pragma unroll
    for (int e = 0; e < NB; e++) { c0[e] = b3lo; c1[e] = b3hi; }
#pragma unroll
    for (int kc = 0; kc < 8; kc++) {
        float4 v[NB];
#pragma unroll
        for (int e = 0; e < NB; e++)
            v[e] = reinterpret_cast<const float4*>(su)[e * 16 + kc];
        float wl0 = sW3T[(4 * kc + 0) * 64 + lane];
        float wh0 = sW3T[(4 * kc + 0) * 64 + lane + 32];
        float wl1 = sW3T[(4 * kc + 1) * 64 + lane];
        float wh1 = sW3T[(4 * kc + 1) * 64 + lane + 32];
        float wl2 = sW3T[(4 * kc + 2) * 64 + lane];
        float wh2 = sW3T[(4 * kc + 2) * 64 + lane + 32];
        float wl3 = sW3T[(4 * kc + 3) * 64 + lane];
        float wh3 = sW3T[(4 * kc + 3) * 64 + lane + 32];
#pragma unroll
        for (int e = 0; e < NB; e++) {
            c0[e] = fmaf(v[e].x, wl0, c0[e]);
            c1[e] = fmaf(v[e].x, wh0, c1[e]);
            c0[e] = fmaf(v[e].y, wl1, c0[e]);
            c1[e] = fmaf(v[e].y, wh1, c1[e]);
            c0[e] = fmaf(v[e].z, wl2, c0[e]);
            c1[e] = fmaf(v[e].z, wh2, c1[e]);
            c0[e] = fmaf(v[e].w, wl3, c0[e]);
            c1[e] = fmaf(v[e].w, wh3, c1[e]);
        }
    }
#pragma unroll
    for (int e = 0; e < NB; e++) { olo[e] = c0[e]; ohi[e] = c1[e]; }
}

// 64->64 GEMV: out[i] = b[i] + sum_{k<64} u[k] * M[i,k], M transposed in sM.
__device__ __forceinline__ void gemv64(
    const float* __restrict__ sM, const float* su, int lane,
    float blo, float bhi, float* olo, float* ohi)
{
    float c0[NB], c1[NB];
#pragma unroll
    for (int e = 0; e < NB; e++) { c0[e] = blo; c1[e] = bhi; }
#pragma unroll
    for (int kc = 0; kc < 16; kc++) {
        float4 v[NB];
#pragma unroll
        for (int e = 0; e < NB; e++)
            v[e] = reinterpret_cast<const float4*>(su)[e * 16 + kc];
        float wl0 = sM[(4 * kc + 0) * 64 + lane];
        float wh0 = sM[(4 * kc + 0) * 64 + lane + 32];
        float wl1 = sM[(4 * kc + 1) * 64 + lane];
        float wh1 = sM[(4 * kc + 1) * 64 + lane + 32];
        float wl2 = sM[(4 * kc + 2) * 64 + lane];
        float wh2 = sM[(4 * kc + 2) * 64 + lane + 32];
        float wl3 = sM[(4 * kc + 3) * 64 + lane];
        float wh3 = sM[(4 * kc + 3) * 64 + lane + 32];
#pragma unroll
        for (int e = 0; e < NB; e++) {
            c0[e] = fmaf(v[e].x, wl0, c0[e]);
            c1[e] = fmaf(v[e].x, wh0, c1[e]);
            c0[e] = fmaf(v[e].y, wl1, c0[e]);
            c1[e] = fmaf(v[e].y, wh1, c1[e]);
            c0[e] = fmaf(v[e].z, wl2, c0[e]);
            c1[e] = fmaf(v[e].z, wh2, c1[e]);
            c0[e] = fmaf(v[e].w, wl3, c0[e]);
            c1[e] = fmaf(v[e].w, wh3, c1[e]);
        }
    }
#pragma unroll
    for (int e = 0; e < NB; e++) { olo[e] = c0[e]; ohi[e] = c1[e]; }
}

__global__ __launch_bounds__(THREADS)
void node_kernel(
    const float* __restrict__ ts, const float* __restrict__ y0,
    const float* __restrict__ encW, const float* __restrict__ encb,
    const float* __restrict__ W1, const float* __restrict__ b1,
    const float* __restrict__ W2, const float* __restrict__ b2,
    const float* __restrict__ W3, const float* __restrict__ b3,
    const float* __restrict__ decW, const float* __restrict__ decb,
    float* __restrict__ ys, float* __restrict__ zs)
{
    __shared__ float sW1T[64 * 32];
    __shared__ float sW2T[32 * 32];
    __shared__ float sW3T[32 * 64];
    __shared__ float sBig[64 * 64];                 // enc^T first, then dec^T
    __shared__ float sUall[WARPS * NB * 64];

    const int tid = threadIdx.x;
    const int lane = tid & 31;
    const int wid = tid >> 5;
    float* su = &sUall[wid * NB * 64];

    // Stage transposed weights
    for (int i = tid; i < 64 * 32; i += THREADS) {
        int k = i >> 5, j = i & 31;
        sW1T[i] = W1[j * 64 + k];
    }
    for (int i = tid; i < 32 * 32; i += THREADS) {
        int k = i >> 5, j = i & 31;
        sW2T[i] = W2[j * 32 + k];
    }
    for (int i = tid; i < 32 * 64; i += THREADS) {
        int k = i >> 6, j = i & 63;
        sW3T[i] = W3[j * 32 + k];
    }
    for (int i = tid; i < 64 * 64; i += THREADS) {
        int k = i >> 6, j = i & 63;
        sBig[i] = encW[j * 64 + k];                 // enc^T
    }
    __syncthreads();

    const float b1r = b1[lane];
    const float b2r = b2[lane];
    const float b3lo = b3[lane];
    const float b3hi = b3[lane + 32];
    const float ebl = encb[lane];
    const float ebh = encb[lane + 32];

    const float dt = (ts[kT - 1] - ts[0]) * (1.0f / (float)NSTEPS);

    const float dA21 = dt * cA21;
    const float dA31 = dt * cA31, dA32 = dt * cA32;
    const float dA41 = dt * cA41, dA42 = dt * cA42, dA43 = dt * cA43;
    const float dA51 = dt * cA51, dA52 = dt * cA52, dA53 = dt * cA53, dA54 = dt * cA54;
    const float dA61 = dt * cA61, dA62 = dt * cA62, dA63 = dt * cA63, dA64 = dt * cA64, dA65 = dt * cA65;
    const float dB1 = dt * cB1, dB2 = dt * cB2, dB3 = dt * cB3;
    const float dB4 = dt * cB4, dB5 = dt * cB5, dB6 = dt * cB6;

    const int elt0 = blockIdx.x * ELEMS_PER_BLOCK + wid * NB;

    // ---- encoder: z0 = y0 @ encW^T + encb ----
#pragma unroll
    for (int e = 0; e < NB; e++) {
        su[e * 64 + lane]      = y0[(size_t)(elt0 + e) * 64 + lane];
        su[e * 64 + lane + 32] = y0[(size_t)(elt0 + e) * 64 + lane + 32];
    }
    __syncwarp();
    float z0[NB], z1[NB];
    gemv64(sBig, su, lane, ebl, ebh, z0, z1);

    __syncthreads();   // all warps done reading enc^T
    for (int i = tid; i < 64 * 64; i += THREADS) {
        int k = i >> 6, j = i & 63;
        sBig[i] = decW[j * 64 + k];                 // dec^T
    }
    __syncthreads();

    const float dbl = decb[lane];
    const float dbh = decb[lane + 32];

    float k1l[NB], k1h[NB], k2l[NB], k2h[NB], k3l[NB], k3h[NB];
    float k4l[NB], k4h[NB], k5l[NB], k5h[NB], k6l[NB], k6h[NB];
    float yl[NB], yh[NB];

#pragma unroll 1
    for (int t = 0; t <= NSTEPS; t++) {
        // publish z_t to shared (used by decode and by k1 = f(z))
        __syncwarp();
#pragma unroll
        for (int e = 0; e < NB; e++) {
            su[e * 64 + lane]      = z0[e];
            su[e * 64 + lane + 32] = z1[e];
        }
        __syncwarp();

        // write zs[b, t, :]
#pragma unroll
        for (int e = 0; e < NB; e++) {
            size_t base = ((size_t)(elt0 + e) * kT + t) * kH;
            zs[base + lane]      = z0[e];
            zs[base + lane + 32] = z1[e];
        }
        // decode + write ys[b, t, :]
        gemv64(sBig, su, lane, dbl, dbh, yl, yh);
#pragma unroll
        for (int e = 0; e < NB; e++) {
            size_t base = ((size_t)(elt0 + e) * kT + t) * kH;
            ys[base + lane]      = yl[e];
            ys[base + lane + 32] = yh[e];
        }
        if (t == NSTEPS) break;

        // ---- Tsit5 step ----
        mlp_eval(sW1T, sW2T, sW3T, b1r, b2r, b3lo, b3hi, su, lane, k1l, k1h);

        __syncwarp();
#pragma unroll
        for (int e = 0; e < NB; e++) {
            su[e * 64 + lane]      = fmaf(dA21, k1l[e], z0[e]);
            su[e * 64 + lane + 32] = fmaf(dA21, k1h[e], z1[e]);
        }
        __syncwarp();
        mlp_eval(sW1T, sW2T, sW3T, b1r, b2r, b3lo, b3hi, su, lane, k2l, k2h);

        __syncwarp();
#pragma unroll
        for (int e = 0; e < NB; e++) {
            float ul = fmaf(dA31, k1l[e], z0[e]); ul = fmaf(dA32, k2l[e], ul);
            float uh = fmaf(dA31, k1h[e], z1[e]); uh = fmaf(dA32, k2h[e], uh);
            su[e * 64 + lane] = ul; su[e * 64 + lane + 32] = uh;
        }
        __syncwarp();
        mlp_eval(sW1T, sW2T, sW3T, b1r, b2r, b3lo, b3hi, su, lane, k3l, k3h);

        __syncwarp();
#pragma unroll
        for (int e = 0; e < NB; e++) {
            float ul = fmaf(dA41, k1l[e], z0[e]);
            ul = fmaf(dA42, k2l[e], ul); ul = fmaf(dA43, k3l[e], ul);
            float uh = fmaf(dA41, k1h[e], z1[e]);
            uh = fmaf(dA42, k2h[e], uh); uh = fmaf(dA43, k3h[e], uh);
            su[e * 64 + lane] = ul; su[e * 64 + lane + 32] = uh;
        }
        __syncwarp();
        mlp_eval(sW1T, sW2T, sW3T, b1r, b2r, b3lo, b3hi, su, lane, k4l, k4h);

        __syncwarp();
#pragma unroll
        for (int e = 0; e < NB; e++) {
            float ul = fmaf(dA51, k1l[e], z0[e]);
            ul = fmaf(dA52, k2l[e], ul); ul = fmaf(dA53, k3l[e], ul);
            ul = fmaf(dA54, k4l[e], ul);
            float uh = fmaf(dA51, k1h[e], z1[e]);
            uh = fmaf(dA52, k2h[e], uh); uh = fmaf(dA53, k3h[e], uh);
            uh = fmaf(dA54, k4h[e], uh);
            su[e * 64 + lane] = ul; su[e * 64 + lane + 32] = uh;
        }
        __syncwarp();
        mlp_eval(sW1T, sW2T, sW3T, b1r, b2r, b3lo, b3hi, su, lane, k5l, k5h);

        __syncwarp();
#pragma unroll
        for (int e = 0; e < NB; e++) {
            float ul = fmaf(dA61, k1l[e], z0[e]);
            ul = fmaf(dA62, k2l[e], ul); ul = fmaf(dA63, k3l[e], ul);
            ul = fmaf(dA64, k4l[e], ul); ul = fmaf(dA65, k5l[e], ul);
            float uh = fmaf(dA61, k1h[e], z1[e]);
            uh = fmaf(dA62, k2h[e], uh); uh = fmaf(dA63, k3h[e], uh);
            uh = fmaf(dA64, k4h[e], uh); uh = fmaf(dA65, k5h[e], uh);
            su[e * 64 + lane] = ul; su[e * 64 + lane + 32] = uh;
        }
        __syncwarp();
        mlp_eval(sW1T, sW2T, sW3T, b1r, b2r, b3lo, b3hi, su, lane, k6l, k6h);

#pragma unroll
        for (int e = 0; e < NB; e++) {
            float zl = z0[e];
            zl = fmaf(dB1, k1l[e], zl); zl = fmaf(dB2, k2l[e], zl);
            zl = fmaf(dB3, k3l[e], zl); zl = fmaf(dB4, k4l[e], zl);
            zl = fmaf(dB5, k5l[e], zl); zl = fmaf(dB6, k6l[e], zl);
            z0[e] = zl;
            float zh = z1[e];
            zh = fmaf(dB1, k1h[e], zh); zh = fmaf(dB2, k2h[e], zh);
            zh = fmaf(dB3, k3h[e], zh); zh = fmaf(dB4, k4h[e], zh);
            zh = fmaf(dB5, k5h[e], zh); zh = fmaf(dB6, k6h[e], zh);
            z1[e] = zh;
        }
    }
}

} // namespace

extern "C" void kernel_launch(void* const* d_in, const int* in_sizes, int n_in,
                              void* d_out, int out_size) {
    const float* ts   = (const float*)d_in[0];
    const float* y0   = (const float*)d_in[1];
    const float* encW = (const float*)d_in[2];
    const float* encb = (const float*)d_in[3];
    const float* W1   = (const float*)d_in[4];
    const float* b1   = (const float*)d_in[5];
    const float* W2   = (const float*)d_in[6];
    const float* b2   = (const float*)d_in[7];
    const float* W3   = (const float*)d_in[8];
    const float* b3   = (const float*)d_in[9];
    const float* decW = (const float*)d_in[10];
    const float* decb = (const float*)d_in[11];

    float* ys = (float*)d_out;
    float* zs = ys + (size_t)out_size / 2;   // [ys | zs], each B*T*64

    node_kernel<<<GRID, THREADS>>>(ts, y0, encW, encb, W1, b1, W2, b2, W3, b3,
                                   decW, decb, ys, zs);
}

// round 2
// speedup vs baseline: 1.1920x; 1.1920x over previous
#include <cuda_runtime.h>
#include <math.h>

// NeuralODE on GB300, round 2.
// Kernel 1 (sequential): z0 = enc(y0), 100 Tsit5 steps of MLP(64->32->32->64,
//   tanh), writes zs[B,T,64]. One warp = one batch element. All MLP weights
//   register-resident, packed over K for fma.rn.f32x2 (FFMA2). Activation
//   broadcast via per-warp SMEM (conflict-free LDS.128).
// Kernel 2 (parallel): ys = zs @ decW^T + decb over all B*T rows, dec weights
//   register-resident, FFMA2.

namespace {

constexpr int kB = 4096;
constexpr int kT = 101;
constexpr int kH = 64;
constexpr int NSTEPS = kT - 1;

constexpr int WARPS = 4;
constexpr int THREADS = WARPS * 32;
constexpr int GRID = kB / WARPS;          // 1024 blocks, 1 elem per warp

// Tsit5 tableau — compile-time constants -> FFMA-imm forms in SASS
constexpr float A21 = 0.161f;
constexpr float A31 = -0.008480655492356989f, A32 = 0.335480655492357f;
constexpr float A41 = 2.8971530571054935f, A42 = -6.359448489975075f, A43 = 4.3622954328695815f;
constexpr float A51 = 5.325864828439257f, A52 = -11.748883564062828f;
constexpr float A53 = 7.4955393428898365f, A54 = -0.09249506636175525f;
constexpr float A61 = 5.86145544294642f, A62 = -12.92096931784711f;
constexpr float A63 = 8.159367898576159f, A64 = -0.071584973281401f, A65 = -0.028269050394068383f;
constexpr float B1c = 0.09646076681806523f, B2c = 0.01f, B3c = 0.4798896504144996f;
constexpr float B4c = 1.379008574103742f, B5c = -3.290069515436081f, B6c = 2.324710524099774f;

using u64 = unsigned long long;

__device__ __forceinline__ u64 pk(float x, float y) {
    u64 r; asm("mov.b64 %0, {%1,%2};" : "=l"(r) : "f"(x), "f"(y)); return r;
}
__device__ __forceinline__ u64 fma2(u64 a, u64 b, u64 c) {
    u64 d; asm("fma.rn.f32x2 %0, %1, %2, %3;" : "=l"(d) : "l"(a), "l"(b), "l"(c)); return d;
}
__device__ __forceinline__ float hsum2(u64 a, u64 b) {
    float ax, ay, bx, by;
    asm("mov.b64 {%0,%1}, %2;" : "=f"(ax), "=f"(ay) : "l"(a));
    asm("mov.b64 {%0,%1}, %2;" : "=f"(bx), "=f"(by) : "l"(b));
    return (ax + ay) + (bx + by);
}
__device__ __forceinline__ float tanh_f(float x) {
    // tanh via exp: ~1e-7 rel err, 2 MUFU
    float ax = fabsf(x);
    float e = __expf(-2.0f * ax);
    float t = __fdividef(1.0f - e, 1.0f + e);
    return copysignf(t, x);
}

__global__ void __launch_bounds__(THREADS)
ode_kernel(
    const float* __restrict__ ts, const float* __restrict__ y0,
    const float* __restrict__ encW, const float* __restrict__ encb,
    const float* __restrict__ W1g, const float* __restrict__ b1g,
    const float* __restrict__ W2g, const float* __restrict__ b2g,
    const float* __restrict__ W3g, const float* __restrict__ b3g,
    float* __restrict__ zs)
{
    __shared__ float sm[WARPS * 128];   // per warp: [0:64)=u, [64:96)=h1, [96:128)=h2
    const int lane = threadIdx.x & 31;
    const int wid = threadIdx.x >> 5;
    float* su = sm + wid * 128;
    float* sh1 = su + 64;
    float* sh2 = su + 96;
    const int b = blockIdx.x * WARPS + wid;

    // ---- register-resident MLP weights, packed over K ----
    u64 w1p[32];   // W1[lane][0..63], 32 k-pairs
    u64 w2p[16];   // W2[lane][0..31]
    u64 w3a[16];   // W3[2*lane][0..31]
    u64 w3b[16];   // W3[2*lane+1][0..31]
    {
        const float4* v1 = reinterpret_cast<const float4*>(W1g + lane * 64);
#pragma unroll
        for (int i = 0; i < 16; i++) {
            float4 v = v1[i];
            w1p[2 * i] = pk(v.x, v.y); w1p[2 * i + 1] = pk(v.z, v.w);
        }
        const float4* v2 = reinterpret_cast<const float4*>(W2g + lane * 32);
#pragma unroll
        for (int i = 0; i < 8; i++) {
            float4 v = v2[i];
            w2p[2 * i] = pk(v.x, v.y); w2p[2 * i + 1] = pk(v.z, v.w);
        }
        const float4* v3a = reinterpret_cast<const float4*>(W3g + (2 * lane) * 32);
        const float4* v3b = reinterpret_cast<const float4*>(W3g + (2 * lane + 1) * 32);
#pragma unroll
        for (int i = 0; i < 8; i++) {
            float4 va = v3a[i], vb = v3b[i];
            w3a[2 * i] = pk(va.x, va.y); w3a[2 * i + 1] = pk(va.z, va.w);
            w3b[2 * i] = pk(vb.x, vb.y); w3b[2 * i + 1] = pk(vb.z, vb.w);
        }
    }
    const float b1r = b1g[lane];
    const float b2r = b2g[lane];
    const float2 b3p = *reinterpret_cast<const float2*>(b3g + 2 * lane);
    const float dt = (ts[kT - 1] - ts[0]) / (float)NSTEPS;

    // ---- encoder: z = enc(y0[b]) ; lane owns components (2*lane, 2*lane+1) ----
    float z0, z1;
    {
        float2 y = *reinterpret_cast<const float2*>(y0 + (size_t)b * 64 + 2 * lane);
        reinterpret_cast<float2*>(su)[lane] = y;
        __syncwarp();
        const float4* Ea = reinterpret_cast<const float4*>(encW + (2 * lane) * 64);
        const float4* Eb = reinterpret_cast<const float4*>(encW + (2 * lane + 1) * 64);
        u64 a0 = 0, a1 = 0, c0 = 0, c1 = 0;
#pragma unroll
        for (int kc = 0; kc < 16; kc++) {
            float4 v = reinterpret_cast<const float4*>(su)[kc];
            u64 p0 = pk(v.x, v.y), p1 = pk(v.z, v.w);
            float4 wa = Ea[kc], wb = Eb[kc];
            a0 = fma2(p0, pk(wa.x, wa.y), a0);
            a1 = fma2(p1, pk(wa.z, wa.w), a1);
            c0 = fma2(p0, pk(wb.x, wb.y), c0);
            c1 = fma2(p1, pk(wb.z, wb.w), c1);
        }
        float2 eb = *reinterpret_cast<const float2*>(encb + 2 * lane);
        z0 = hsum2(a0, a1) + eb.x;
        z1 = hsum2(c0, c1) + eb.y;
        __syncwarp();
    }

    // MLP field eval: input u must already be in su[0..63]; returns (ol, oh)
    // for components (2*lane, 2*lane+1). 3 __syncwarp per eval.
    auto mlp = [&](float& ol, float& oh) {
        // layer 1: 64 -> 32, tanh
        u64 a0 = 0, a1 = 0;
#pragma unroll
        for (int kc = 0; kc < 16; kc++) {
            float4 v = reinterpret_cast<const float4*>(su)[kc];
            a0 = fma2(pk(v.x, v.y), w1p[2 * kc], a0);
            a1 = fma2(pk(v.z, v.w), w1p[2 * kc + 1], a1);
        }
        float h1 = tanh_f(hsum2(a0, a1) + b1r);
        sh1[lane] = h1;
        __syncwarp();
        // layer 2: 32 -> 32, tanh
        u64 c0 = 0, c1 = 0;
#pragma unroll
        for (int kc = 0; kc < 8; kc++) {
            float4 v = reinterpret_cast<const float4*>(sh1)[kc];
            c0 = fma2(pk(v.x, v.y), w2p[2 * kc], c0);
            c1 = fma2(pk(v.z, v.w), w2p[2 * kc + 1], c1);
        }
        float h2 = tanh_f(hsum2(c0, c1) + b2r);
        sh2[lane] = h2;
        __syncwarp();
        // layer 3: 32 -> 64 (outputs 2*lane, 2*lane+1)
        u64 d0 = 0, d1 = 0, e0 = 0, e1 = 0;
#pragma unroll
        for (int kc = 0; kc < 8; kc++) {
            float4 v = reinterpret_cast<const float4*>(sh2)[kc];
            u64 p0 = pk(v.x, v.y), p1 = pk(v.z, v.w);
            d0 = fma2(p0, w3a[2 * kc], d0);
            d1 = fma2(p1, w3a[2 * kc + 1], d1);
            e0 = fma2(p0, w3b[2 * kc], e0);
            e1 = fma2(p1, w3b[2 * kc + 1], e1);
        }
        ol = hsum2(d0, d1) + b3p.x;
        oh = hsum2(e0, e1) + b3p.y;
    };

    auto setu = [&](float ul, float uh) {
        reinterpret_cast<float2*>(su)[lane] = make_float2(ul, uh);
        __syncwarp();
    };

    float k1l, k1h, k2l, k2h, k3l, k3h, k4l, k4h, k5l, k5h, k6l, k6h;

#pragma unroll 1
    for (int t = 0; t < NSTEPS; t++) {
        // store zs[b, t, :]
        reinterpret_cast<float2*>(zs + ((size_t)b * kT + t) * kH)[lane] =
            make_float2(z0, z1);

        setu(z0, z1);
        mlp(k1l, k1h);

        setu(fmaf(dt, A21 * k1l, z0), fmaf(dt, A21 * k1h, z1));
        mlp(k2l, k2h);

        {
            float al = fmaf(A32, k2l, A31 * k1l);
            float ah = fmaf(A32, k2h, A31 * k1h);
            setu(fmaf(dt, al, z0), fmaf(dt, ah, z1));
        }
        mlp(k3l, k3h);

        {
            float al = fmaf(A42, k2l, A41 * k1l); al = fmaf(A43, k3l, al);
            float ah = fmaf(A42, k2h, A41 * k1h); ah = fmaf(A43, k3h, ah);
            setu(fmaf(dt, al, z0), fmaf(dt, ah, z1));
        }
        mlp(k4l, k4h);

        {
            float al = fmaf(A52, k2l, A51 * k1l);
            al = fmaf(A53, k3l, al); al = fmaf(A54, k4l, al);
            float ah = fmaf(A52, k2h, A51 * k1h);
            ah = fmaf(A53, k3h, ah); ah = fmaf(A54, k4h, ah);
            setu(fmaf(dt, al, z0), fmaf(dt, ah, z1));
        }
        mlp(k5l, k5h);

        {
            float al = fmaf(A62, k2l, A61 * k1l);
            al = fmaf(A63, k3l, al); al = fmaf(A64, k4l, al); al = fmaf(A65, k5l, al);
            float ah = fmaf(A62, k2h, A61 * k1h);
            ah = fmaf(A63, k3h, ah); ah = fmaf(A64, k4h, ah); ah = fmaf(A65, k5h, ah);
            setu(fmaf(dt, al, z0), fmaf(dt, ah, z1));
        }
        mlp(k6l, k6h);

        {
            float sl = B1c * k1l;
            sl = fmaf(B2c, k2l, sl); sl = fmaf(B3c, k3l, sl);
            sl = fmaf(B4c, k4l, sl); sl = fmaf(B5c, k5l, sl); sl = fmaf(B6c, k6l, sl);
            z0 = fmaf(dt, sl, z0);
            float sh = B1c * k1h;
            sh = fmaf(B2c, k2h, sh); sh = fmaf(B3c, k3h, sh);
            sh = fmaf(B4c, k4h, sh); sh = fmaf(B5c, k5h, sh); sh = fmaf(B6c, k6h, sh);
            z1 = fmaf(dt, sh, z1);
        }
    }
    // final state zs[b, T-1, :]
    reinterpret_cast<float2*>(zs + ((size_t)b * kT + NSTEPS) * kH)[lane] =
        make_float2(z0, z1);
}

// ---- decode: ys[r, :] = zs[r, :] @ decW^T + decb, r in [0, B*T) ----
constexpr int DEC_THREADS = 256;
constexpr int DEC_GRID = 148 * 4;

__global__ void __launch_bounds__(DEC_THREADS)
dec_kernel(const float* __restrict__ zs, const float* __restrict__ decW,
           const float* __restrict__ decb, float* __restrict__ ys)
{
    const int lane = threadIdx.x & 31;
    const int gw = (int)((blockIdx.x * blockDim.x + threadIdx.x) >> 5);
    const int nw = (int)((gridDim.x * blockDim.x) >> 5);

    // lane owns output components (2*lane, 2*lane+1): 2 rows of decW, packed over K
    u64 wa[32], wb[32];
    {
        const float4* va = reinterpret_cast<const float4*>(decW + (2 * lane) * 64);
        const float4* vb = reinterpret_cast<const float4*>(decW + (2 * lane + 1) * 64);
#pragma unroll
        for (int i = 0; i < 16; i++) {
            float4 x = va[i], y = vb[i];
            wa[2 * i] = pk(x.x, x.y); wa[2 * i + 1] = pk(x.z, x.w);
            wb[2 * i] = pk(y.x, y.y); wb[2 * i + 1] = pk(y.z, y.w);
        }
    }
    const float2 db = *reinterpret_cast<const float2*>(decb + 2 * lane);

    const int R = kB * kT;
#pragma unroll 1
    for (int r = gw; r < R; r += nw) {
        const float4* zr = reinterpret_cast<const float4*>(zs + (size_t)r * 64);
        u64 a0 = 0, a1 = 0, c0 = 0, c1 = 0;
#pragma unroll
        for (int kc = 0; kc < 16; kc++) {
            float4 v = zr[kc];                     // uniform broadcast load
            u64 p0 = pk(v.x, v.y), p1 = pk(v.z, v.w);
            a0 = fma2(p0, wa[2 * kc], a0);
            a1 = fma2(p1, wa[2 * kc + 1], a1);
            c0 = fma2(p0, wb[2 * kc], c0);
            c1 = fma2(p1, wb[2 * kc + 1], c1);
        }
        reinterpret_cast<float2*>(ys + (size_t)r * 64)[lane] =
            make_float2(hsum2(a0, a1) + db.x, hsum2(c0, c1) + db.y);
    }
}

} // namespace

extern "C" void kernel_launch(void* const* d_in, const int* in_sizes, int n_in,
                              void* d_out, int out_size) {
    const float* ts   = (const float*)d_in[0];
    const float* y0   = (const float*)d_in[1];
    const float* encW = (const float*)d_in[2];
    const float* encb = (const float*)d_in[3];
    const float* W1   = (const float*)d_in[4];
    const float* b1   = (const float*)d_in[5];
    const float* W2   = (const float*)d_in[6];
    const float* b2   = (const float*)d_in[7];
    const float* W3   = (const float*)d_in[8];
    const float* b3   = (const float*)d_in[9];
    const float* decW = (const float*)d_in[10];
    const float* decb = (const float*)d_in[11];

    float* ys = (float*)d_out;
    float* zs = ys + (size_t)out_size / 2;     // [ys | zs]

    ode_kernel<<<GRID, THREADS>>>(ts, y0, encW, encb, W1, b1, W2, b2, W3, b3, zs);
    dec_kernel<<<DEC_GRID, DEC_THREADS>>>(zs, decW, decb, ys);
}

// round 3
// speedup vs baseline: 1.6177x; 1.3571x over previous
#include <cuda_runtime.h>
#include <math.h>

// NeuralODE on GB300, round 3.
// ode_kernel: warp owns NB=2 batch elements. MLP weights register-resident,
//   K-packed u64 for fma.rn.f32x2. Activations broadcast via per-warp smem,
//   read back as ulonglong2 (LDS.128 -> two u64, zero pack movs). Biases
//   folded into accumulator init. 5-instr tanh.
// dec_kernel: smem-staged row tiles, register-resident FFMA2 dec weights,
//   128-thread blocks for 3 blocks/SM occupancy.

namespace {

constexpr int kB = 4096;
constexpr int kT = 101;
constexpr int kH = 64;
constexpr int NSTEPS = kT - 1;

constexpr int NB = 2;                       // elements per warp
constexpr int WARPS = 4;                    // warps per block
constexpr int THREADS = WARPS * 32;
constexpr int ELEMS_PER_BLOCK = WARPS * NB; // 8
constexpr int GRID = kB / ELEMS_PER_BLOCK;  // 512

// Tsit5 tableau (compile-time immediates -> FFMA-imm rt1 forms)
constexpr float A21 = 0.161f;
constexpr float A31 = -0.008480655492356989f, A32 = 0.335480655492357f;
constexpr float A41 = 2.8971530571054935f, A42 = -6.359448489975075f, A43 = 4.3622954328695815f;
constexpr float A51 = 5.325864828439257f, A52 = -11.748883564062828f;
constexpr float A53 = 7.4955393428898365f, A54 = -0.09249506636175525f;
constexpr float A61 = 5.86145544294642f, A62 = -12.92096931784711f;
constexpr float A63 = 8.159367898576159f, A64 = -0.071584973281401f, A65 = -0.028269050394068383f;
constexpr float B1c = 0.09646076681806523f, B2c = 0.01f, B3c = 0.4798896504144996f;
constexpr float B4c = 1.379008574103742f, B5c = -3.290069515436081f, B6c = 2.324710524099774f;

using u64 = unsigned long long;

__device__ __forceinline__ u64 pk(float x, float y) {
    u64 r; asm("mov.b64 %0, {%1,%2};" : "=l"(r) : "f"(x), "f"(y)); return r;
}
__device__ __forceinline__ u64 fma2(u64 a, u64 b, u64 c) {
    u64 d; asm("fma.rn.f32x2 %0, %1, %2, %3;" : "=l"(d) : "l"(a), "l"(b), "l"(c)); return d;
}
__device__ __forceinline__ float hsum2(u64 a, u64 b) {
    float ax, ay, bx, by;
    asm("mov.b64 {%0,%1}, %2;" : "=f"(ax), "=f"(ay) : "l"(a));
    asm("mov.b64 {%0,%1}, %2;" : "=f"(bx), "=f"(by) : "l"(b));
    return (ax + ay) + (bx + by);
}
__device__ __forceinline__ float tanh_f(float x) {
    // tanh(x) = 1 - 2/(e^{2x}+1). Correct limits at +-inf. ~1e-7 rel err.
    float ex;
    asm("ex2.approx.f32 %0, %1;" : "=f"(ex) : "f"(x * 2.885390081777927f));
    float r;
    asm("rcp.approx.f32 %0, %1;" : "=f"(r) : "f"(ex + 1.0f));
    return fmaf(-2.0f, r, 1.0f);
}

__global__ void __launch_bounds__(THREADS)
ode_kernel(
    const float* __restrict__ ts, const float* __restrict__ y0,
    const float* __restrict__ encW, const float* __restrict__ encb,
    const float* __restrict__ W1g, const float* __restrict__ b1g,
    const float* __restrict__ W2g, const float* __restrict__ b2g,
    const float* __restrict__ W3g, const float* __restrict__ b3g,
    float* __restrict__ zs)
{
    // per warp: suA[64] suB[64] sh1A[32] sh1B[32] sh2A[32] sh2B[32] = 256 f
    __shared__ __align__(16) float sm[WARPS * 256];
    const int lane = threadIdx.x & 31;
    const int wid = threadIdx.x >> 5;
    float* suA  = sm + wid * 256;
    float* suB  = suA + 64;
    float* sh1A = suA + 128;
    float* sh1B = suA + 160;
    float* sh2A = suA + 192;
    float* sh2B = suA + 224;
    const int bA = blockIdx.x * ELEMS_PER_BLOCK + wid * NB;
    const int bB = bA + 1;

    // ---- register-resident MLP weights, K-packed ----
    u64 w1p[32];   // W1[lane][0..63]
    u64 w2p[16];   // W2[lane][0..31]
    u64 w3a[16];   // W3[2*lane][0..31]
    u64 w3b[16];   // W3[2*lane+1][0..31]
    {
        const ulonglong2* v1 = reinterpret_cast<const ulonglong2*>(W1g + lane * 64);
#pragma unroll
        for (int i = 0; i < 16; i++) { ulonglong2 v = v1[i]; w1p[2*i] = v.x; w1p[2*i+1] = v.y; }
        const ulonglong2* v2 = reinterpret_cast<const ulonglong2*>(W2g + lane * 32);
#pragma unroll
        for (int i = 0; i < 8; i++) { ulonglong2 v = v2[i]; w2p[2*i] = v.x; w2p[2*i+1] = v.y; }
        const ulonglong2* v3a = reinterpret_cast<const ulonglong2*>(W3g + (2*lane) * 32);
        const ulonglong2* v3b = reinterpret_cast<const ulonglong2*>(W3g + (2*lane+1) * 32);
#pragma unroll
        for (int i = 0; i < 8; i++) {
            ulonglong2 a = v3a[i], b = v3b[i];
            w3a[2*i] = a.x; w3a[2*i+1] = a.y;
            w3b[2*i] = b.x; w3b[2*i+1] = b.y;
        }
    }
    const float b1r = b1g[lane];
    const float b2r = b2g[lane];
    const float2 b3p = *reinterpret_cast<const float2*>(b3g + 2 * lane);
    const float dt = (ts[kT - 1] - ts[0]) / (float)NSTEPS;

    // ---- encoder for both elements ----
    float zA0, zA1, zB0, zB1;
    {
        reinterpret_cast<float2*>(suA)[lane] =
            *reinterpret_cast<const float2*>(y0 + (size_t)bA * 64 + 2 * lane);
        reinterpret_cast<float2*>(suB)[lane] =
            *reinterpret_cast<const float2*>(y0 + (size_t)bB * 64 + 2 * lane);
        __syncwarp();
        const ulonglong2* Ea = reinterpret_cast<const ulonglong2*>(encW + (2*lane) * 64);
        const ulonglong2* Eb = reinterpret_cast<const ulonglong2*>(encW + (2*lane+1) * 64);
        const float2 eb = *reinterpret_cast<const float2*>(encb + 2 * lane);
        u64 aA0 = pk(eb.x, 0.f), aA1 = 0, cA0 = pk(eb.y, 0.f), cA1 = 0;
        u64 aB0 = pk(eb.x, 0.f), aB1 = 0, cB0 = pk(eb.y, 0.f), cB1 = 0;
        const ulonglong2* uA = reinterpret_cast<const ulonglong2*>(suA);
        const ulonglong2* uB = reinterpret_cast<const ulonglong2*>(suB);
#pragma unroll
        for (int kc = 0; kc < 16; kc++) {
            ulonglong2 wA = Ea[kc], wB = Eb[kc];
            ulonglong2 vA = uA[kc], vB = uB[kc];
            aA0 = fma2(vA.x, wA.x, aA0); aA1 = fma2(vA.y, wA.y, aA1);
            cA0 = fma2(vA.x, wB.x, cA0); cA1 = fma2(vA.y, wB.y, cA1);
            aB0 = fma2(vB.x, wA.x, aB0); aB1 = fma2(vB.y, wA.y, aB1);
            cB0 = fma2(vB.x, wB.x, cB0); cB1 = fma2(vB.y, wB.y, cB1);
        }
        zA0 = hsum2(aA0, aA1); zA1 = hsum2(cA0, cA1);
        zB0 = hsum2(aB0, aB1); zB1 = hsum2(cB0, cB1);
        __syncwarp();
    }

    // MLP field eval for both elements; input in suA/suB.
    auto mlp2 = [&](float& oAl, float& oAh, float& oBl, float& oBh) {
        // layer 1: 64 -> 32, tanh
        u64 aA0 = pk(b1r, 0.f), aA1 = 0, aB0 = pk(b1r, 0.f), aB1 = 0;
        {
            const ulonglong2* uA = reinterpret_cast<const ulonglong2*>(suA);
            const ulonglong2* uB = reinterpret_cast<const ulonglong2*>(suB);
#pragma unroll
            for (int kc = 0; kc < 16; kc++) {
                ulonglong2 vA = uA[kc], vB = uB[kc];
                aA0 = fma2(vA.x, w1p[2*kc], aA0); aA1 = fma2(vA.y, w1p[2*kc+1], aA1);
                aB0 = fma2(vB.x, w1p[2*kc], aB0); aB1 = fma2(vB.y, w1p[2*kc+1], aB1);
            }
        }
        sh1A[lane] = tanh_f(hsum2(aA0, aA1));
        sh1B[lane] = tanh_f(hsum2(aB0, aB1));
        __syncwarp();
        // layer 2: 32 -> 32, tanh
        u64 cA0 = pk(b2r, 0.f), cA1 = 0, cB0 = pk(b2r, 0.f), cB1 = 0;
        {
            const ulonglong2* hA = reinterpret_cast<const ulonglong2*>(sh1A);
            const ulonglong2* hB = reinterpret_cast<const ulonglong2*>(sh1B);
#pragma unroll
            for (int kc = 0; kc < 8; kc++) {
                ulonglong2 vA = hA[kc], vB = hB[kc];
                cA0 = fma2(vA.x, w2p[2*kc], cA0); cA1 = fma2(vA.y, w2p[2*kc+1], cA1);
                cB0 = fma2(vB.x, w2p[2*kc], cB0); cB1 = fma2(vB.y, w2p[2*kc+1], cB1);
            }
        }
        sh2A[lane] = tanh_f(hsum2(cA0, cA1));
        sh2B[lane] = tanh_f(hsum2(cB0, cB1));
        __syncwarp();
        // layer 3: 32 -> 64 (lane outputs comps 2*lane, 2*lane+1)
        u64 dA0 = pk(b3p.x, 0.f), dA1 = 0, eA0 = pk(b3p.y, 0.f), eA1 = 0;
        u64 dB0 = pk(b3p.x, 0.f), dB1 = 0, eB0 = pk(b3p.y, 0.f), eB1 = 0;
        {
            const ulonglong2* hA = reinterpret_cast<const ulonglong2*>(sh2A);
            const ulonglong2* hB = reinterpret_cast<const ulonglong2*>(sh2B);
#pragma unroll
            for (int kc = 0; kc < 8; kc++) {
                ulonglong2 vA = hA[kc], vB = hB[kc];
                dA0 = fma2(vA.x, w3a[2*kc], dA0); dA1 = fma2(vA.y, w3a[2*kc+1], dA1);
                eA0 = fma2(vA.x, w3b[2*kc], eA0); eA1 = fma2(vA.y, w3b[2*kc+1], eA1);
                dB0 = fma2(vB.x, w3a[2*kc], dB0); dB1 = fma2(vB.y, w3a[2*kc+1], dB1);
                eB0 = fma2(vB.x, w3b[2*kc], eB0); eB1 = fma2(vB.y, w3b[2*kc+1], eB1);
            }
        }
        oAl = hsum2(dA0, dA1); oAh = hsum2(eA0, eA1);
        oBl = hsum2(dB0, dB1); oBh = hsum2(eB0, eB1);
    };

    auto setu2 = [&](float uAl, float uAh, float uBl, float uBh) {
        reinterpret_cast<float2*>(suA)[lane] = make_float2(uAl, uAh);
        reinterpret_cast<float2*>(suB)[lane] = make_float2(uBl, uBh);
        __syncwarp();
    };

    float k1Al, k1Ah, k2Al, k2Ah, k3Al, k3Ah, k4Al, k4Ah, k5Al, k5Ah, k6Al, k6Ah;
    float k1Bl, k1Bh, k2Bl, k2Bh, k3Bl, k3Bh, k4Bl, k4Bh, k5Bl, k5Bh, k6Bl, k6Bh;

#pragma unroll 1
    for (int t = 0; t < NSTEPS; t++) {
        reinterpret_cast<float2*>(zs + ((size_t)bA * kT + t) * kH)[lane] = make_float2(zA0, zA1);
        reinterpret_cast<float2*>(zs + ((size_t)bB * kT + t) * kH)[lane] = make_float2(zB0, zB1);

        setu2(zA0, zA1, zB0, zB1);
        mlp2(k1Al, k1Ah, k1Bl, k1Bh);

        setu2(fmaf(dt, A21 * k1Al, zA0), fmaf(dt, A21 * k1Ah, zA1),
              fmaf(dt, A21 * k1Bl, zB0), fmaf(dt, A21 * k1Bh, zB1));
        mlp2(k2Al, k2Ah, k2Bl, k2Bh);

        {
            float aAl = fmaf(A32, k2Al, A31 * k1Al), aAh = fmaf(A32, k2Ah, A31 * k1Ah);
            float aBl = fmaf(A32, k2Bl, A31 * k1Bl), aBh = fmaf(A32, k2Bh, A31 * k1Bh);
            setu2(fmaf(dt, aAl, zA0), fmaf(dt, aAh, zA1),
                  fmaf(dt, aBl, zB0), fmaf(dt, aBh, zB1));
        }
        mlp2(k3Al, k3Ah, k3Bl, k3Bh);

        {
            float aAl = fmaf(A42, k2Al, A41 * k1Al); aAl = fmaf(A43, k3Al, aAl);
            float aAh = fmaf(A42, k2Ah, A41 * k1Ah); aAh = fmaf(A43, k3Ah, aAh);
            float aBl = fmaf(A42, k2Bl, A41 * k1Bl); aBl = fmaf(A43, k3Bl, aBl);
            float aBh = fmaf(A42, k2Bh, A41 * k1Bh); aBh = fmaf(A43, k3Bh, aBh);
            setu2(fmaf(dt, aAl, zA0), fmaf(dt, aAh, zA1),
                  fmaf(dt, aBl, zB0), fmaf(dt, aBh, zB1));
        }
        mlp2(k4Al, k4Ah, k4Bl, k4Bh);

        {
            float aAl = fmaf(A52, k2Al, A51 * k1Al); aAl = fmaf(A53, k3Al, aAl); aAl = fmaf(A54, k4Al, aAl);
            float aAh = fmaf(A52, k2Ah, A51 * k1Ah); aAh = fmaf(A53, k3Ah, aAh); aAh = fmaf(A54, k4Ah, aAh);
            float aBl = fmaf(A52, k2Bl, A51 * k1Bl); aBl = fmaf(A53, k3Bl, aBl); aBl = fmaf(A54, k4Bl, aBl);
            float aBh = fmaf(A52, k2Bh, A51 * k1Bh); aBh = fmaf(A53, k3Bh, aBh); aBh = fmaf(A54, k4Bh, aBh);
            setu2(fmaf(dt, aAl, zA0), fmaf(dt, aAh, zA1),
                  fmaf(dt, aBl, zB0), fmaf(dt, aBh, zB1));
        }
        mlp2(k5Al, k5Ah, k5Bl, k5Bh);

        {
            float aAl = fmaf(A62, k2Al, A61 * k1Al); aAl = fmaf(A63, k3Al, aAl);
            aAl = fmaf(A64, k4Al, aAl); aAl = fmaf(A65, k5Al, aAl);
            float aAh = fmaf(A62, k2Ah, A61 * k1Ah); aAh = fmaf(A63, k3Ah, aAh);
            aAh = fmaf(A64, k4Ah, aAh); aAh = fmaf(A65, k5Ah, aAh);
            float aBl = fmaf(A62, k2Bl, A61 * k1Bl); aBl = fmaf(A63, k3Bl, aBl);
            aBl = fmaf(A64, k4Bl, aBl); aBl = fmaf(A65, k5Bl, aBl);
            float aBh = fmaf(A62, k2Bh, A61 * k1Bh); aBh = fmaf(A63, k3Bh, aBh);
            aBh = fmaf(A64, k4Bh, aBh); aBh = fmaf(A65, k5Bh, aBh);
            setu2(fmaf(dt, aAl, zA0), fmaf(dt, aAh, zA1),
                  fmaf(dt, aBl, zB0), fmaf(dt, aBh, zB1));
        }
        mlp2(k6Al, k6Ah, k6Bl, k6Bh);

        {
            float s;
            s = B1c * k1Al; s = fmaf(B2c, k2Al, s); s = fmaf(B3c, k3Al, s);
            s = fmaf(B4c, k4Al, s); s = fmaf(B5c, k5Al, s); s = fmaf(B6c, k6Al, s);
            zA0 = fmaf(dt, s, zA0);
            s = B1c * k1Ah; s = fmaf(B2c, k2Ah, s); s = fmaf(B3c, k3Ah, s);
            s = fmaf(B4c, k4Ah, s); s = fmaf(B5c, k5Ah, s); s = fmaf(B6c, k6Ah, s);
            zA1 = fmaf(dt, s, zA1);
            s = B1c * k1Bl; s = fmaf(B2c, k2Bl, s); s = fmaf(B3c, k3Bl, s);
            s = fmaf(B4c, k4Bl, s); s = fmaf(B5c, k5Bl, s); s = fmaf(B6c, k6Bl, s);
            zB0 = fmaf(dt, s, zB0);
            s = B1c * k1Bh; s = fmaf(B2c, k2Bh, s); s = fmaf(B3c, k3Bh, s);
            s = fmaf(B4c, k4Bh, s); s = fmaf(B5c, k5Bh, s); s = fmaf(B6c, k6Bh, s);
            zB1 = fmaf(dt, s, zB1);
        }
    }
    reinterpret_cast<float2*>(zs + ((size_t)bA * kT + NSTEPS) * kH)[lane] = make_float2(zA0, zA1);
    reinterpret_cast<float2*>(zs + ((size_t)bB * kT + NSTEPS) * kH)[lane] = make_float2(zB0, zB1);
}

// ---- decode: ys = zs @ decW^T + decb, smem-staged tiles ----
constexpr int DEC_THREADS = 128;
constexpr int DEC_TILE = 16;                        // rows per tile
constexpr int DEC_GRID = 444;                       // ~3 blocks/SM

__global__ void __launch_bounds__(DEC_THREADS)
dec_kernel(const float* __restrict__ zs, const float* __restrict__ decW,
           const float* __restrict__ decb, float* __restrict__ ys)
{
    __shared__ __align__(16) float sz[DEC_TILE * 64];
    const int tid = threadIdx.x;
    const int lane = tid & 31;
    const int wid = tid >> 5;

    // lane owns output comps (2*lane, 2*lane+1): decW rows K-packed in regs
    u64 wa[32], wb[32];
    {
        const ulonglong2* va = reinterpret_cast<const ulonglong2*>(decW + (2*lane) * 64);
        const ulonglong2* vb = reinterpret_cast<const ulonglong2*>(decW + (2*lane+1) * 64);
#pragma unroll
        for (int i = 0; i < 16; i++) {
            ulonglong2 x = va[i], y = vb[i];
            wa[2*i] = x.x; wa[2*i+1] = x.y;
            wb[2*i] = y.x; wb[2*i+1] = y.y;
        }
    }
    const float2 db = *reinterpret_cast<const float2*>(decb + 2 * lane);

    const int nTiles = (kB * kT) / DEC_TILE;   // 25856
#pragma unroll 1
    for (int tile = blockIdx.x; tile < nTiles; tile += DEC_GRID) {
        // stage 16 rows (1024 floats) coalesced
        const float4* g = reinterpret_cast<const float4*>(zs + (size_t)tile * DEC_TILE * 64);
        float4* s4 = reinterpret_cast<float4*>(sz);
        s4[tid] = g[tid];
        s4[tid + 128] = g[tid + 128];
        __syncthreads();

        const int r0 = wid * 4;
#pragma unroll
        for (int rr = 0; rr < 4; rr++) {
            const ulonglong2* zr = reinterpret_cast<const ulonglong2*>(sz + (r0 + rr) * 64);
            u64 a0 = pk(db.x, 0.f), a1 = 0, c0 = pk(db.y, 0.f), c1 = 0;
#pragma unroll
            for (int kc = 0; kc < 16; kc++) {
                ulonglong2 v = zr[kc];
                a0 = fma2(v.x, wa[2*kc], a0); a1 = fma2(v.y, wa[2*kc+1], a1);
                c0 = fma2(v.x, wb[2*kc], c0); c1 = fma2(v.y, wb[2*kc+1], c1);
            }
            const size_t row = (size_t)tile * DEC_TILE + r0 + rr;
            reinterpret_cast<float2*>(ys + row * 64)[lane] =
                make_float2(hsum2(a0, a1), hsum2(c0, c1));
        }
        __syncthreads();
    }
}

} // namespace

extern "C" void kernel_launch(void* const* d_in, const int* in_sizes, int n_in,
                              void* d_out, int out_size) {
    const float* ts   = (const float*)d_in[0];
    const float* y0   = (const float*)d_in[1];
    const float* encW = (const float*)d_in[2];
    const float* encb = (const float*)d_in[3];
    const float* W1   = (const float*)d_in[4];
    const float* b1   = (const float*)d_in[5];
    const float* W2   = (const float*)d_in[6];
    const float* b2   = (const float*)d_in[7];
    const float* W3   = (const float*)d_in[8];
    const float* b3   = (const float*)d_in[9];
    const float* decW = (const float*)d_in[10];
    const float* decb = (const float*)d_in[11];

    float* ys = (float*)d_out;
    float* zs = ys + (size_t)out_size / 2;     // [ys | zs]

    ode_kernel<<<GRID, THREADS>>>(ts, y0, encW, encb, W1, b1, W2, b2, W3, b3, zs);
    dec_kernel<<<DEC_GRID, DEC_THREADS>>>(zs, decW, decb, ys);
}